// round 1
// baseline (speedup 1.0000x reference)
#include <cuda_runtime.h>
#include <math.h>

// Problem constants
#define Bc 4
#define Sc 4096
#define Dc 128
#define Kc 64
#define Vc 128
#define BSc (Bc*Sc)          // 16384 tokens
#define OUTC (Dc + Vc)       // 256

// ---------------------------------------------------------------------------
// Scratch (device globals; no allocation allowed)
// ---------------------------------------------------------------------------
__device__ float g_Q [BSc * Kc];            // 4 MB   [b*S+s][k]
__device__ float g_Kp[BSc * Kc];            // 4 MB
__device__ float g_Vp[BSc * Vc];            // 8 MB
__device__ float g_E [(size_t)Bc * Sc * Sc];// 256 MB  exp(scores), causal region
__device__ float g_denom[BSc];              // column sums per (b, j)

// ---------------------------------------------------------------------------
// Kernel 0: zero denominators (atomics accumulate into them each launch)
// ---------------------------------------------------------------------------
__global__ void zden_kernel() {
    int i = blockIdx.x * 256 + threadIdx.x;
    if (i < BSc) g_denom[i] = 0.0f;
}

// ---------------------------------------------------------------------------
// Kernel 1: projections  Q = xWq^T + bq ; K = xWk^T + bk ; V = xWv^T + bv
// grid (BS/64, 4): y = 0:Q, 1:K, 2:V[:,0:64], 3:V[:,64:128]
// block tile: 64 tokens x 64 outputs, reduce over D=128
// ---------------------------------------------------------------------------
__global__ void proj_kernel(const float* __restrict__ x,
                            const float* __restrict__ Wq, const float* __restrict__ bq,
                            const float* __restrict__ Wk, const float* __restrict__ bk,
                            const float* __restrict__ Wv, const float* __restrict__ bv) {
    const int g  = blockIdx.y;
    const int t0 = blockIdx.x * 64;

    const float* W;  const float* bias;  float* out;  int ostride, ncol0;
    if (g == 0)      { W = Wq;           bias = bq;      out = g_Q;  ostride = Kc; ncol0 = 0;  }
    else if (g == 1) { W = Wk;           bias = bk;      out = g_Kp; ostride = Kc; ncol0 = 0;  }
    else if (g == 2) { W = Wv;           bias = bv;      out = g_Vp; ostride = Vc; ncol0 = 0;  }
    else             { W = Wv + 64 * Dc; bias = bv + 64; out = g_Vp; ostride = Vc; ncol0 = 64; }

    __shared__ float As[64][17];
    __shared__ float Ws[64][17];

    const int tid = threadIdx.x;
    const int ty = tid / 16, tx = tid % 16;

    float acc[4][4] = {};

    const int li = tid / 4;          // row 0..63 for loads
    const int lk = (tid % 4) * 4;    // k offset 0,4,8,12

    for (int kk = 0; kk < Dc; kk += 16) {
        float4 a4 = *(const float4*)&x[(size_t)(t0 + li) * Dc + kk + lk];
        As[li][lk+0] = a4.x; As[li][lk+1] = a4.y; As[li][lk+2] = a4.z; As[li][lk+3] = a4.w;
        float4 w4 = *(const float4*)&W[(size_t)li * Dc + kk + lk];
        Ws[li][lk+0] = w4.x; Ws[li][lk+1] = w4.y; Ws[li][lk+2] = w4.z; Ws[li][lk+3] = w4.w;
        __syncthreads();
        #pragma unroll
        for (int k = 0; k < 16; k++) {
            float a[4], b[4];
            #pragma unroll
            for (int r = 0; r < 4; r++) a[r] = As[ty*4+r][k];
            #pragma unroll
            for (int c = 0; c < 4; c++) b[c] = Ws[tx*4+c][k];
            #pragma unroll
            for (int r = 0; r < 4; r++)
                #pragma unroll
                for (int c = 0; c < 4; c++)
                    acc[r][c] += a[r] * b[c];
        }
        __syncthreads();
    }

    #pragma unroll
    for (int r = 0; r < 4; r++) {
        #pragma unroll
        for (int c = 0; c < 4; c++) {
            int col = tx*4 + c;
            out[(size_t)(t0 + ty*4 + r) * ostride + ncol0 + col] = acc[r][c] + bias[col];
        }
    }
}

// ---------------------------------------------------------------------------
// Kernel 2: E[q,j] = exp(Q.K^T / 8) on causal tiles; accumulate column sums.
// grid (2080, B): linear index over lower-triangular 64x64 tile pairs (qt>=jt)
// ---------------------------------------------------------------------------
__global__ void scores_kernel() {
    const int b   = blockIdx.y;
    const int lin = blockIdx.x;

    // triangular index -> (qt, jt), qt >= jt
    int qt = (int)((sqrtf(8.0f * (float)lin + 1.0f) - 1.0f) * 0.5f);
    while ((qt + 1) * (qt + 2) / 2 <= lin) qt++;
    while (qt * (qt + 1) / 2 > lin) qt--;
    const int jt = lin - qt * (qt + 1) / 2;

    const int q0 = qt * 64, j0 = jt * 64;
    const float* Qb = g_Q  + (size_t)b * Sc * Kc;
    const float* Kb = g_Kp + (size_t)b * Sc * Kc;

    __shared__ float Qs[64][17];
    __shared__ float Ks[64][17];
    __shared__ float csum[64];

    const int tid = threadIdx.x;
    const int ty = tid / 16, tx = tid % 16;
    if (tid < 64) csum[tid] = 0.0f;

    float acc[4][4] = {};
    const int li = tid / 4;
    const int lk = (tid % 4) * 4;

    for (int kk = 0; kk < Kc; kk += 16) {
        float4 q4 = *(const float4*)&Qb[(size_t)(q0 + li) * Kc + kk + lk];
        Qs[li][lk+0] = q4.x; Qs[li][lk+1] = q4.y; Qs[li][lk+2] = q4.z; Qs[li][lk+3] = q4.w;
        float4 k4 = *(const float4*)&Kb[(size_t)(j0 + li) * Kc + kk + lk];
        Ks[li][lk+0] = k4.x; Ks[li][lk+1] = k4.y; Ks[li][lk+2] = k4.z; Ks[li][lk+3] = k4.w;
        __syncthreads();
        #pragma unroll
        for (int k = 0; k < 16; k++) {
            float a[4], bb[4];
            #pragma unroll
            for (int r = 0; r < 4; r++) a[r]  = Qs[ty*4+r][k];
            #pragma unroll
            for (int c = 0; c < 4; c++) bb[c] = Ks[tx*4+c][k];
            #pragma unroll
            for (int r = 0; r < 4; r++)
                #pragma unroll
                for (int c = 0; c < 4; c++)
                    acc[r][c] += a[r] * bb[c];
        }
        __syncthreads();
    }

    float* Eb = g_E + (size_t)b * Sc * Sc;
    #pragma unroll
    for (int r = 0; r < 4; r++) {
        const int q = q0 + ty*4 + r;
        float e[4];
        float colacc[4];
        #pragma unroll
        for (int c = 0; c < 4; c++) {
            const int j = j0 + tx*4 + c;
            float s = acc[r][c] * 0.125f;       // 1/sqrt(K), K=64
            e[c] = (j <= q) ? __expf(s) : 0.0f; // causal mask
            colacc[c] = e[c];
        }
        float4 ev = make_float4(e[0], e[1], e[2], e[3]);
        *(float4*)&Eb[(size_t)q * Sc + j0 + tx*4] = ev;
        #pragma unroll
        for (int c = 0; c < 4; c++)
            atomicAdd(&csum[tx*4 + c], colacc[c]);
    }
    __syncthreads();
    if (tid < 64)
        atomicAdd(&g_denom[b * Sc + j0 + tid], csum[tid]);
}

// ---------------------------------------------------------------------------
// Kernel 3: out[:, :, 0:128] = x ; out[:, :, 128:256] = 0
// ---------------------------------------------------------------------------
__global__ void concat_kernel(const float* __restrict__ x, float* __restrict__ out) {
    size_t idx = (size_t)blockIdx.x * 256 + threadIdx.x;   // < BSc*OUTC
    int c = (int)(idx % OUTC);
    size_t t = idx / OUTC;
    out[idx] = (c < Dc) ? x[t * Dc + c] : 0.0f;
}

// ---------------------------------------------------------------------------
// Kernel 4: attention += E @ (V / denom[j])   (causal, j-split + atomicAdd)
// grid (544, B). Each block: 64 q-rows x 128 v-cols, j-chunk of 256.
// ---------------------------------------------------------------------------
#define JCHUNK 256
__global__ void attn_kernel(float* __restrict__ out) {
    const int b   = blockIdx.y;
    const int lin = blockIdx.x;

    // linear -> (qt, chunk): chunks(qt) = ceil((qt+1)/4)
    int qt = 0, base = 0;
    for (;;) {
        int c = (qt + 4) >> 2;
        if (lin < base + c) break;
        base += c; qt++;
    }
    const int chunk = lin - base;
    const int q0 = qt * 64;
    const int j_begin = chunk * JCHUNK;
    const int j_end   = min(q0 + 64, j_begin + JCHUNK);   // exclusive, mult of 16

    const float* Eb = g_E  + (size_t)b * Sc * Sc;
    const float* Vb = g_Vp + (size_t)b * Sc * Vc;
    const float* db = g_denom + b * Sc;

    __shared__ float Es[64][17];
    __shared__ float Ws[16][128];

    const int tid = threadIdx.x;
    const int ty = tid / 16, tx = tid % 16;

    float acc[4][8] = {};

    const int li = tid / 4;          // E row
    const int lk = (tid % 4) * 4;    // E j offset
    const int jr = tid >> 4;         // W row 0..15
    const int cb = (tid & 15) * 8;   // W col base

    for (int j0 = j_begin; j0 < j_end; j0 += 16) {
        float4 e4 = *(const float4*)&Eb[(size_t)(q0 + li) * Sc + j0 + lk];
        Es[li][lk+0] = e4.x; Es[li][lk+1] = e4.y; Es[li][lk+2] = e4.z; Es[li][lk+3] = e4.w;

        float inv = 1.0f / db[j0 + jr];
        const float* vp = &Vb[(size_t)(j0 + jr) * Vc + cb];
        float4 w0 = *(const float4*)vp;
        float4 w1 = *(const float4*)(vp + 4);
        Ws[jr][cb+0] = w0.x * inv; Ws[jr][cb+1] = w0.y * inv;
        Ws[jr][cb+2] = w0.z * inv; Ws[jr][cb+3] = w0.w * inv;
        Ws[jr][cb+4] = w1.x * inv; Ws[jr][cb+5] = w1.y * inv;
        Ws[jr][cb+6] = w1.z * inv; Ws[jr][cb+7] = w1.w * inv;
        __syncthreads();

        #pragma unroll
        for (int k = 0; k < 16; k++) {
            float a[4];
            #pragma unroll
            for (int r = 0; r < 4; r++) a[r] = Es[ty*4+r][k];
            float4 b0 = *(const float4*)&Ws[k][tx*8];
            float4 b1 = *(const float4*)&Ws[k][tx*8 + 4];
            #pragma unroll
            for (int r = 0; r < 4; r++) {
                acc[r][0] += a[r]*b0.x; acc[r][1] += a[r]*b0.y;
                acc[r][2] += a[r]*b0.z; acc[r][3] += a[r]*b0.w;
                acc[r][4] += a[r]*b1.x; acc[r][5] += a[r]*b1.y;
                acc[r][6] += a[r]*b1.z; acc[r][7] += a[r]*b1.w;
            }
        }
        __syncthreads();
    }

    #pragma unroll
    for (int r = 0; r < 4; r++) {
        size_t row = (size_t)(b * Sc + q0 + ty*4 + r) * OUTC + Dc + tx*8;
        #pragma unroll
        for (int c = 0; c < 8; c++)
            atomicAdd(&out[row + c], acc[r][c]);
    }
}

// ---------------------------------------------------------------------------
// Launch
// ---------------------------------------------------------------------------
extern "C" void kernel_launch(void* const* d_in, const int* in_sizes, int n_in,
                              void* d_out, int out_size) {
    const float* x  = (const float*)d_in[0];
    const float* Wq = (const float*)d_in[1];
    const float* bq = (const float*)d_in[2];
    const float* Wk = (const float*)d_in[3];
    const float* bk = (const float*)d_in[4];
    const float* Wv = (const float*)d_in[5];
    const float* bv = (const float*)d_in[6];
    float* out = (float*)d_out;

    zden_kernel<<<(BSc + 255) / 256, 256>>>();
    proj_kernel<<<dim3(BSc / 64, 4), 256>>>(x, Wq, bq, Wk, bk, Wv, bv);
    scores_kernel<<<dim3(2080, Bc), 256>>>();          // 64*65/2 causal tiles
    concat_kernel<<<(BSc * OUTC) / 256, 256>>>(x, out);
    attn_kernel<<<dim3(544, Bc), 256>>>(out);          // sum ceil((qt+1)/4)
}